// round 1
// baseline (speedup 1.0000x reference)
#include <cuda_runtime.h>
#include <math.h>
#include <stdint.h>

#define NN_ 4096
#define EE_ 262144
#define HID_ 256
#define DOUT_ 128
#define HEADS_ 4
#define DH_ 64
#define L_ 4096

// ---------------- scratch (all static __device__, no allocations) ----------------
__device__ float g_deg[NN_];
__device__ float g_dinv[NN_];
__device__ int   g_cnt[NN_];
__device__ int   g_rowptr[NN_ + 1];
__device__ int   g_fill[NN_];
__device__ int   g_src[EE_];
__device__ float g_w[EE_];

__device__ float g_h[NN_ * HID_];       // pre-aggregation GEMM output
__device__ float g_a[NN_ * HID_];       // gcn output
__device__ float g_b[NN_ * HID_];       // mha output
__device__ float g_qkv[NN_ * 3 * HID_];
__device__ float g_attn[NN_ * HID_];
__device__ float g_scores[(size_t)HEADS_ * L_ * L_];   // 268 MB

// ---------------- preprocessing ----------------
__global__ void k_init() {
    int i = blockIdx.x * blockDim.x + threadIdx.x;
    if (i < NN_) { g_deg[i] = 1.0f; g_cnt[i] = 0; }
}

__global__ void k_deg(const int* __restrict__ ei, const float* __restrict__ ew) {
    int e = blockIdx.x * blockDim.x + threadIdx.x;
    if (e < EE_) {
        int c = ei[EE_ + e];
        atomicAdd(&g_deg[c], ew[e]);
        atomicAdd(&g_cnt[c], 1);
    }
}

__global__ void k_dinv() {
    int i = blockIdx.x * blockDim.x + threadIdx.x;
    if (i < NN_) {
        float d = g_deg[i];
        g_dinv[i] = (d > 0.f) ? rsqrtf(d) : 0.f;
    }
}

// one-block exclusive scan of g_cnt -> g_rowptr / g_fill   (1024 threads x 4)
__global__ void k_scan() {
    __shared__ int partial[1024];
    int t = threadIdx.x;
    int base = t * 4;
    int c0 = g_cnt[base + 0], c1 = g_cnt[base + 1], c2 = g_cnt[base + 2], c3 = g_cnt[base + 3];
    int s = c0 + c1 + c2 + c3;
    partial[t] = s;
    __syncthreads();
    for (int off = 1; off < 1024; off <<= 1) {
        int v = 0;
        if (t >= off) v = partial[t - off];
        __syncthreads();
        partial[t] += v;
        __syncthreads();
    }
    int run = partial[t] - s;   // exclusive prefix for this thread's chunk
    g_rowptr[base + 0] = run; g_fill[base + 0] = run; run += c0;
    g_rowptr[base + 1] = run; g_fill[base + 1] = run; run += c1;
    g_rowptr[base + 2] = run; g_fill[base + 2] = run; run += c2;
    g_rowptr[base + 3] = run; g_fill[base + 3] = run; run += c3;
    if (t == 1023) g_rowptr[NN_] = run;
}

__global__ void k_fill(const int* __restrict__ ei, const float* __restrict__ ew) {
    int e = blockIdx.x * blockDim.x + threadIdx.x;
    if (e < EE_) {
        int r = ei[e];
        int c = ei[EE_ + e];
        int pos = atomicAdd(&g_fill[c], 1);
        g_src[pos] = r;
        g_w[pos] = g_dinv[r] * ew[e] * g_dinv[c];   // full sym-norm coefficient
    }
}

// ---------------- tiled fp32 GEMM  C = alpha * A @ op(B) (+bias)(+relu) ----------------
// TRANSB=0: B is [K,Nn] row-major.  TRANSB=1: B is [Nn,K] row-major (C=A@B^T).
// EPI: 0 none, 1 +bias, 2 +bias+relu
template <int TRANSB, int EPI>
__global__ void __launch_bounds__(256) gemm_kernel(
    const float* __restrict__ A, int lda,
    const float* __restrict__ B, int ldb,
    const float* __restrict__ bias,
    float* __restrict__ C, int ldc,
    int M, int Nn, int K, float alpha)
{
    __shared__ float As[16][64];
    __shared__ float Bs[16][64];
    const int bm = blockIdx.y * 64;
    const int bn = blockIdx.x * 64;
    const int tid = threadIdx.x;
    const int tx = tid & 15;
    const int ty = tid >> 4;
    const int lrow = tid >> 2;            // 0..63
    const int lcol = (tid & 3) << 2;      // 0,4,8,12

    float acc[4][4];
#pragma unroll
    for (int i = 0; i < 4; i++)
#pragma unroll
        for (int j = 0; j < 4; j++) acc[i][j] = 0.f;

    for (int kt = 0; kt < K; kt += 16) {
        float4 av = *reinterpret_cast<const float4*>(&A[(size_t)(bm + lrow) * lda + kt + lcol]);
        As[lcol + 0][lrow] = av.x;
        As[lcol + 1][lrow] = av.y;
        As[lcol + 2][lrow] = av.z;
        As[lcol + 3][lrow] = av.w;
        if (TRANSB) {
            float4 bv = *reinterpret_cast<const float4*>(&B[(size_t)(bn + lrow) * ldb + kt + lcol]);
            Bs[lcol + 0][lrow] = bv.x;
            Bs[lcol + 1][lrow] = bv.y;
            Bs[lcol + 2][lrow] = bv.z;
            Bs[lcol + 3][lrow] = bv.w;
        } else {
            const int brow = tid >> 4;          // 0..15
            const int bcol = (tid & 15) << 2;   // 0..60
            float4 bv = *reinterpret_cast<const float4*>(&B[(size_t)(kt + brow) * ldb + bn + bcol]);
            *reinterpret_cast<float4*>(&Bs[brow][bcol]) = bv;
        }
        __syncthreads();
#pragma unroll
        for (int kk = 0; kk < 16; kk++) {
            float4 a4 = *reinterpret_cast<const float4*>(&As[kk][ty << 2]);
            float4 b4 = *reinterpret_cast<const float4*>(&Bs[kk][tx << 2]);
            float a[4] = {a4.x, a4.y, a4.z, a4.w};
            float b[4] = {b4.x, b4.y, b4.z, b4.w};
#pragma unroll
            for (int i = 0; i < 4; i++)
#pragma unroll
                for (int j = 0; j < 4; j++) acc[i][j] += a[i] * b[j];
        }
        __syncthreads();
    }

#pragma unroll
    for (int i = 0; i < 4; i++) {
        int r = bm + (ty << 2) + i;
        int c = bn + (tx << 2);
        float4 o;
        float v0 = acc[i][0] * alpha, v1 = acc[i][1] * alpha;
        float v2 = acc[i][2] * alpha, v3 = acc[i][3] * alpha;
        if (EPI >= 1) {
            v0 += bias[c + 0]; v1 += bias[c + 1]; v2 += bias[c + 2]; v3 += bias[c + 3];
        }
        if (EPI == 2) {
            v0 = fmaxf(v0, 0.f); v1 = fmaxf(v1, 0.f); v2 = fmaxf(v2, 0.f); v3 = fmaxf(v3, 0.f);
        }
        o.x = v0; o.y = v1; o.z = v2; o.w = v3;
        *reinterpret_cast<float4*>(&C[(size_t)r * ldc + c]) = o;
    }
}

// ---------------- row softmax over [rows, L] ----------------
__global__ void __launch_bounds__(256) softmax_rows(float* __restrict__ S) {
    __shared__ float row[L_];
    __shared__ float red[256];
    float* r = S + (size_t)blockIdx.x * L_;
    int t = threadIdx.x;
    float m = -1e30f;
    for (int i = t; i < L_; i += 256) {
        float v = r[i];
        row[i] = v;
        m = fmaxf(m, v);
    }
    red[t] = m;
    __syncthreads();
    for (int off = 128; off; off >>= 1) {
        if (t < off) red[t] = fmaxf(red[t], red[t + off]);
        __syncthreads();
    }
    m = red[0];
    __syncthreads();
    float s = 0.f;
    for (int i = t; i < L_; i += 256) {
        float e = __expf(row[i] - m);
        row[i] = e;
        s += e;
    }
    red[t] = s;
    __syncthreads();
    for (int off = 128; off; off >>= 1) {
        if (t < off) red[t] += red[t + off];
        __syncthreads();
    }
    float inv = 1.f / red[0];
    for (int i = t; i < L_; i += 256) r[i] = row[i] * inv;
}

// ---------------- GCN aggregation (CSR gather, deterministic-ish, no float atomics) ----------------
// out[c][f] = act( dinv[c]^2*h[c][f] + sum_e w[e]*h[src[e]][f] + bias[f] )
__global__ void gcn_aggregate(const float* __restrict__ h, const float* __restrict__ bias,
                              float* __restrict__ out, int dout, int act)
{
    int c = blockIdx.x;
    int f = threadIdx.x;
    float dv = g_dinv[c];
    float acc = dv * dv * h[(size_t)c * dout + f];
    int e0 = g_rowptr[c], e1 = g_rowptr[c + 1];
    for (int e = e0; e < e1; e++) {
        int s = g_src[e];
        float w = g_w[e];
        acc += w * h[(size_t)s * dout + f];
    }
    acc += bias[f];
    if (act) acc = 1.f / (1.f + __expf(-acc));
    out[(size_t)c * dout + f] = acc;
}

// ---------------- host orchestration ----------------
static inline dim3 gemm_grid(int M, int Nn) { return dim3(Nn / 64, M / 64); }

static void run_mha(const float* x, float* outbuf,
                    const float* ipw, const float* ipb,
                    const float* opw, const float* opb,
                    float* qkv, float* scores, float* attn)
{
    // qkv = x @ in_proj_w^T + in_proj_b     [4096, 768]
    gemm_kernel<1, 1><<<gemm_grid(NN_, 3 * HID_), 256>>>(
        x, HID_, ipw, HID_, ipb, qkv, 3 * HID_, NN_, 3 * HID_, HID_, 1.0f);

    // per-head S = (Q K^T) / 8
    for (int hh = 0; hh < HEADS_; hh++) {
        const float* Q = qkv + hh * DH_;
        const float* Kp = qkv + HID_ + hh * DH_;
        float* S = scores + (size_t)hh * L_ * L_;
        gemm_kernel<1, 0><<<gemm_grid(L_, L_), 256>>>(
            Q, 3 * HID_, Kp, 3 * HID_, nullptr, S, L_, L_, L_, DH_, 0.125f);
    }

    softmax_rows<<<HEADS_ * L_, 256>>>(scores);

    // per-head O = P @ V    -> attn[:, h*64:(h+1)*64]
    for (int hh = 0; hh < HEADS_; hh++) {
        const float* V = qkv + 2 * HID_ + hh * DH_;
        float* S = scores + (size_t)hh * L_ * L_;
        gemm_kernel<0, 0><<<gemm_grid(L_, DH_), 256>>>(
            S, L_, V, 3 * HID_, nullptr, attn + hh * DH_, HID_, L_, DH_, L_, 1.0f);
    }

    // out = relu(attn @ out_proj_w^T + out_proj_b)
    gemm_kernel<1, 2><<<gemm_grid(NN_, HID_), 256>>>(
        attn, HID_, opw, HID_, opb, outbuf, HID_, NN_, HID_, HID_, 1.0f);
}

extern "C" void kernel_launch(void* const* d_in, const int* in_sizes, int n_in,
                              void* d_out, int out_size)
{
    const float* x_in = (const float*)d_in[0];
    const int*   ei   = (const int*)d_in[1];
    const float* ew   = (const float*)d_in[2];
    const float* W1   = (const float*)d_in[3];
    const float* b1   = (const float*)d_in[4];
    const float* W2   = (const float*)d_in[5];
    const float* b2   = (const float*)d_in[6];
    const float* W3   = (const float*)d_in[7];
    const float* b3   = (const float*)d_in[8];
    const float* ipw  = (const float*)d_in[9];
    const float* ipb  = (const float*)d_in[10];
    const float* opw  = (const float*)d_in[11];
    const float* opb  = (const float*)d_in[12];
    float* out = (float*)d_out;

    float *ph, *pa, *pb, *pqkv, *pattn, *pscores;
    cudaGetSymbolAddress((void**)&ph, g_h);
    cudaGetSymbolAddress((void**)&pa, g_a);
    cudaGetSymbolAddress((void**)&pb, g_b);
    cudaGetSymbolAddress((void**)&pqkv, g_qkv);
    cudaGetSymbolAddress((void**)&pattn, g_attn);
    cudaGetSymbolAddress((void**)&pscores, g_scores);

    // --- graph preprocessing (CSR + sym norm), recomputed every launch ---
    k_init<<<NN_ / 256, 256>>>();
    k_deg<<<EE_ / 256, 256>>>(ei, ew);
    k_dinv<<<NN_ / 256, 256>>>();
    k_scan<<<1, 1024>>>();
    k_fill<<<EE_ / 256, 256>>>(ei, ew);

    // --- layer 1: gcn ---
    gemm_kernel<0, 0><<<gemm_grid(NN_, HID_), 256>>>(
        x_in, 256, W1, HID_, nullptr, ph, HID_, NN_, HID_, 256, 1.0f);
    gcn_aggregate<<<NN_, HID_>>>(ph, b1, pa, HID_, 0);

    // --- mha 1 (with relu) ---
    run_mha(pa, pb, ipw, ipb, opw, opb, pqkv, pscores, pattn);

    // --- layer 2: gcn ---
    gemm_kernel<0, 0><<<gemm_grid(NN_, HID_), 256>>>(
        pb, HID_, W2, HID_, nullptr, ph, HID_, NN_, HID_, HID_, 1.0f);
    gcn_aggregate<<<NN_, HID_>>>(ph, b2, pa, HID_, 0);

    // --- mha 2 (with relu) ---
    run_mha(pa, pb, ipw, ipb, opw, opb, pqkv, pscores, pattn);

    // --- layer 3: gcn + sigmoid -> d_out ---
    gemm_kernel<0, 0><<<gemm_grid(NN_, DOUT_), 256>>>(
        pb, HID_, W3, DOUT_, nullptr, ph, DOUT_, NN_, DOUT_, HID_, 1.0f);
    gcn_aggregate<<<NN_, DOUT_>>>(ph, b3, out, DOUT_, 1);
}

// round 2
// speedup vs baseline: 3.0037x; 3.0037x over previous
#include <cuda_runtime.h>
#include <math.h>
#include <stdint.h>

#define NN_ 4096
#define EE_ 262144
#define HID_ 256
#define DOUT_ 128
#define HEADS_ 4
#define DH_ 64
#define L_ 4096
#define KSPLIT_ 4

// ---------------- scratch (all static __device__, no allocations) ----------------
__device__ float g_deg[NN_];
__device__ float g_dinv[NN_];
__device__ int   g_cnt[NN_];
__device__ int   g_rowptr[NN_ + 1];
__device__ int   g_fill[NN_];
__device__ int   g_src[EE_];
__device__ float g_w[EE_];

__device__ float g_h[NN_ * HID_];
__device__ float g_a[NN_ * HID_];
__device__ float g_b[NN_ * HID_];
__device__ float g_qkv[NN_ * 3 * HID_];
__device__ float g_attn[NN_ * HID_];
__device__ float g_pvpart[KSPLIT_ * NN_ * HID_];
__device__ float g_scores[(size_t)HEADS_ * L_ * L_];   // 268 MB

// ---------------- preprocessing ----------------
__global__ void k_init() {
    int i = blockIdx.x * blockDim.x + threadIdx.x;
    if (i < NN_) { g_deg[i] = 1.0f; g_cnt[i] = 0; }
}

__global__ void k_deg(const int* __restrict__ ei, const float* __restrict__ ew) {
    int e = blockIdx.x * blockDim.x + threadIdx.x;
    if (e < EE_) {
        int c = ei[EE_ + e];
        atomicAdd(&g_deg[c], ew[e]);
        atomicAdd(&g_cnt[c], 1);
    }
}

__global__ void k_dinv() {
    int i = blockIdx.x * blockDim.x + threadIdx.x;
    if (i < NN_) {
        float d = g_deg[i];
        g_dinv[i] = (d > 0.f) ? rsqrtf(d) : 0.f;
    }
}

__global__ void k_scan() {
    __shared__ int partial[1024];
    int t = threadIdx.x;
    int base = t * 4;
    int c0 = g_cnt[base + 0], c1 = g_cnt[base + 1], c2 = g_cnt[base + 2], c3 = g_cnt[base + 3];
    int s = c0 + c1 + c2 + c3;
    partial[t] = s;
    __syncthreads();
    for (int off = 1; off < 1024; off <<= 1) {
        int v = 0;
        if (t >= off) v = partial[t - off];
        __syncthreads();
        partial[t] += v;
        __syncthreads();
    }
    int run = partial[t] - s;
    g_rowptr[base + 0] = run; g_fill[base + 0] = run; run += c0;
    g_rowptr[base + 1] = run; g_fill[base + 1] = run; run += c1;
    g_rowptr[base + 2] = run; g_fill[base + 2] = run; run += c2;
    g_rowptr[base + 3] = run; g_fill[base + 3] = run; run += c3;
    if (t == 1023) g_rowptr[NN_] = run;
}

__global__ void k_fill(const int* __restrict__ ei, const float* __restrict__ ew) {
    int e = blockIdx.x * blockDim.x + threadIdx.x;
    if (e < EE_) {
        int r = ei[e];
        int c = ei[EE_ + e];
        int pos = atomicAdd(&g_fill[c], 1);
        g_src[pos] = r;
        g_w[pos] = g_dinv[r] * ew[e] * g_dinv[c];
    }
}

// ---------------- tensor-core tf32 GEMM ----------------
__device__ __forceinline__ uint32_t f2tf(float x) {
    uint32_t u;
    asm("cvt.rna.tf32.f32 %0, %1;" : "=r"(u) : "f"(x));
    return u;
}

// C = alpha * A @ op(B) (+bias)(+relu)
// TRANSB=0: B is [K,Nn] row-major.  TRANSB=1: B is [Nn,K] row-major (C=A@B^T).
// EPI: 0 none, 1 +bias, 2 +bias+relu
// Batched via blockIdx.z: z = batch*KS + kslice. Slice ks computes K-range
// [ks*K/KS, (ks+1)*K/KS) and writes C + batch*sCz + ks*sCk.
template <int TRANSB, int EPI, int KS>
__global__ void __launch_bounds__(256, 2) tc_gemm(
    const float* __restrict__ A, int lda, long sAz,
    const float* __restrict__ B, int ldb, long sBz,
    const float* __restrict__ bias,
    float* __restrict__ C, int ldc, long sCz, long sCk,
    int K, float alpha)
{
    constexpr int BM = 128, BN = 64, BK = 32, LDS_ = BK + 4;  // stride 36
    __shared__ uint32_t As[BM * LDS_];
    __shared__ uint32_t Bs[BN * LDS_];

    const int batch = blockIdx.z / KS;
    const int slice = blockIdx.z % KS;
    A += (long)batch * sAz;
    B += (long)batch * sBz;
    C += (long)batch * sCz + (long)slice * sCk;
    const int k0 = slice * (K / KS);
    const int k1 = k0 + K / KS;

    const int bm = blockIdx.y * BM;
    const int bn = blockIdx.x * BN;
    const int tid = threadIdx.x;
    const int lane = tid & 31;
    const int warp = tid >> 5;
    const int wm = (warp & 3) * 32;   // warp M offset within tile
    const int wn = (warp >> 2) * 32;  // warp N offset within tile
    const int gr = lane >> 2;         // groupID
    const int gc = lane & 3;          // threadID in group

    float acc[2][4][4];
#pragma unroll
    for (int mt = 0; mt < 2; mt++)
#pragma unroll
        for (int nt = 0; nt < 4; nt++)
#pragma unroll
            for (int q = 0; q < 4; q++) acc[mt][nt][q] = 0.f;

    for (int kt = k0; kt < k1; kt += BK) {
        // ---- stage A tile [BM x BK] ----
        {
            const int m = tid >> 1;
            const int kc = (tid & 1) * 16;
            const float* p = A + (size_t)(bm + m) * lda + kt + kc;
            uint32_t* s = &As[m * LDS_ + kc];
#pragma unroll
            for (int j = 0; j < 16; j += 4) {
                float4 v = *reinterpret_cast<const float4*>(p + j);
                s[j + 0] = f2tf(v.x);
                s[j + 1] = f2tf(v.y);
                s[j + 2] = f2tf(v.z);
                s[j + 3] = f2tf(v.w);
            }
        }
        // ---- stage B tile as Bs[n][k] ----
        if (TRANSB) {
            const int n = tid >> 2;
            const int kc = (tid & 3) * 8;
            const float* p = B + (size_t)(bn + n) * ldb + kt + kc;
            uint32_t* s = &Bs[n * LDS_ + kc];
#pragma unroll
            for (int j = 0; j < 8; j += 4) {
                float4 v = *reinterpret_cast<const float4*>(p + j);
                s[j + 0] = f2tf(v.x);
                s[j + 1] = f2tf(v.y);
                s[j + 2] = f2tf(v.z);
                s[j + 3] = f2tf(v.w);
            }
        } else {
            const int k = tid >> 3;
            const int n0 = (tid & 7) * 8;
            const float* p = B + (size_t)(kt + k) * ldb + bn + n0;
#pragma unroll
            for (int j = 0; j < 8; j += 4) {
                float4 v = *reinterpret_cast<const float4*>(p + j);
                Bs[(n0 + j + 0) * LDS_ + k] = f2tf(v.x);
                Bs[(n0 + j + 1) * LDS_ + k] = f2tf(v.y);
                Bs[(n0 + j + 2) * LDS_ + k] = f2tf(v.z);
                Bs[(n0 + j + 3) * LDS_ + k] = f2tf(v.w);
            }
        }
        __syncthreads();

#pragma unroll
        for (int ks = 0; ks < BK; ks += 8) {
            uint32_t af[2][4];
#pragma unroll
            for (int mt = 0; mt < 2; mt++) {
                const uint32_t* a = &As[(wm + mt * 16 + gr) * LDS_ + ks + gc];
                af[mt][0] = a[0];
                af[mt][1] = a[8 * LDS_];
                af[mt][2] = a[4];
                af[mt][3] = a[8 * LDS_ + 4];
            }
#pragma unroll
            for (int nt = 0; nt < 4; nt++) {
                const uint32_t* b = &Bs[(wn + nt * 8 + gr) * LDS_ + ks + gc];
                uint32_t bf0 = b[0];
                uint32_t bf1 = b[4];
#pragma unroll
                for (int mt = 0; mt < 2; mt++) {
                    asm volatile(
                        "mma.sync.aligned.m16n8k8.row.col.f32.tf32.tf32.f32 "
                        "{%0,%1,%2,%3}, {%4,%5,%6,%7}, {%8,%9}, {%0,%1,%2,%3};"
                        : "+f"(acc[mt][nt][0]), "+f"(acc[mt][nt][1]),
                          "+f"(acc[mt][nt][2]), "+f"(acc[mt][nt][3])
                        : "r"(af[mt][0]), "r"(af[mt][1]), "r"(af[mt][2]), "r"(af[mt][3]),
                          "r"(bf0), "r"(bf1));
                }
            }
        }
        __syncthreads();
    }

    // ---- epilogue ----
#pragma unroll
    for (int mt = 0; mt < 2; mt++) {
#pragma unroll
        for (int nt = 0; nt < 4; nt++) {
            const int col = bn + wn + nt * 8 + gc * 2;
            float bx = 0.f, by = 0.f;
            if (EPI >= 1) { bx = bias[col]; by = bias[col + 1]; }
#pragma unroll
            for (int half = 0; half < 2; half++) {
                const int row = bm + wm + mt * 16 + gr + half * 8;
                float v0 = acc[mt][nt][half * 2 + 0] * alpha;
                float v1 = acc[mt][nt][half * 2 + 1] * alpha;
                if (EPI >= 1) { v0 += bx; v1 += by; }
                if (EPI == 2) { v0 = fmaxf(v0, 0.f); v1 = fmaxf(v1, 0.f); }
                *reinterpret_cast<float2*>(&C[(size_t)row * ldc + col]) = make_float2(v0, v1);
            }
        }
    }
}

// sum the KSPLIT_ PV partials into attn
__global__ void k_reduce_pv(float* __restrict__ attn) {
    int i = blockIdx.x * blockDim.x + threadIdx.x;  // over NN_*HID_/4
    const float4* p = reinterpret_cast<const float4*>(g_pvpart);
    const int stride = NN_ * HID_ / 4;
    float4 a = p[i];
    float4 b = p[i + stride];
    float4 c = p[i + 2 * stride];
    float4 d = p[i + 3 * stride];
    float4 o;
    o.x = (a.x + b.x) + (c.x + d.x);
    o.y = (a.y + b.y) + (c.y + d.y);
    o.z = (a.z + b.z) + (c.z + d.z);
    o.w = (a.w + b.w) + (c.w + d.w);
    reinterpret_cast<float4*>(attn)[i] = o;
}

// ---------------- row softmax over [rows, L] ----------------
__global__ void __launch_bounds__(256) softmax_rows(float* __restrict__ S) {
    __shared__ float row[L_];
    __shared__ float red[256];
    float* r = S + (size_t)blockIdx.x * L_;
    int t = threadIdx.x;
    float m = -1e30f;
    for (int i = t; i < L_; i += 256) {
        float v = r[i];
        row[i] = v;
        m = fmaxf(m, v);
    }
    red[t] = m;
    __syncthreads();
    for (int off = 128; off; off >>= 1) {
        if (t < off) red[t] = fmaxf(red[t], red[t + off]);
        __syncthreads();
    }
    m = red[0];
    __syncthreads();
    float s = 0.f;
    for (int i = t; i < L_; i += 256) {
        float e = __expf(row[i] - m);
        row[i] = e;
        s += e;
    }
    red[t] = s;
    __syncthreads();
    for (int off = 128; off; off >>= 1) {
        if (t < off) red[t] += red[t + off];
        __syncthreads();
    }
    float inv = 1.f / red[0];
    for (int i = t; i < L_; i += 256) r[i] = row[i] * inv;
}

// ---------------- GCN aggregation (CSR gather) ----------------
__global__ void gcn_aggregate(const float* __restrict__ h, const float* __restrict__ bias,
                              float* __restrict__ out, int dout, int act)
{
    int c = blockIdx.x;
    int f = threadIdx.x;
    float dv = g_dinv[c];
    float acc = dv * dv * h[(size_t)c * dout + f];
    int e0 = g_rowptr[c], e1 = g_rowptr[c + 1];
    for (int e = e0; e < e1; e++) {
        int s = g_src[e];
        float w = g_w[e];
        acc += w * h[(size_t)s * dout + f];
    }
    acc += bias[f];
    if (act) acc = 1.f / (1.f + __expf(-acc));
    out[(size_t)c * dout + f] = acc;
}

// ---------------- host orchestration ----------------
static void run_mha(const float* x, float* outbuf,
                    const float* ipw, const float* ipb,
                    const float* opw, const float* opb,
                    float* qkv, float* scores, float* attn, float* pvpart)
{
    // qkv = x @ in_proj_w^T + in_proj_b     [4096, 768]
    tc_gemm<1, 1, 1><<<dim3(12, 32, 1), 256>>>(
        x, HID_, 0, ipw, HID_, 0, ipb, qkv, 3 * HID_, 0, 0, HID_, 1.0f);

    // per-head S = (Q K^T) / 8, batched over z = head
    tc_gemm<1, 0, 1><<<dim3(64, 32, HEADS_), 256>>>(
        qkv, 3 * HID_, DH_,
        qkv + HID_, 3 * HID_, DH_,
        nullptr,
        scores, L_, (long)L_ * L_, 0,
        DH_, 0.125f);

    softmax_rows<<<HEADS_ * L_, 256>>>(scores);

    // per-head O = P @ V, split-K=4, z = head*4 + slice
    tc_gemm<0, 0, KSPLIT_><<<dim3(1, 32, HEADS_ * KSPLIT_), 256>>>(
        scores, L_, (long)L_ * L_,
        qkv + 2 * HID_, 3 * HID_, DH_,
        nullptr,
        pvpart, HID_, DH_, (long)NN_ * HID_,
        L_, 1.0f);
    k_reduce_pv<<<NN_ * HID_ / 4 / 256, 256>>>(attn);

    // out = relu(attn @ out_proj_w^T + out_proj_b)
    tc_gemm<1, 2, 1><<<dim3(4, 32, 1), 256>>>(
        attn, HID_, 0, opw, HID_, 0, opb, outbuf, HID_, 0, 0, HID_, 1.0f);
}

extern "C" void kernel_launch(void* const* d_in, const int* in_sizes, int n_in,
                              void* d_out, int out_size)
{
    const float* x_in = (const float*)d_in[0];
    const int*   ei   = (const int*)d_in[1];
    const float* ew   = (const float*)d_in[2];
    const float* W1   = (const float*)d_in[3];
    const float* b1   = (const float*)d_in[4];
    const float* W2   = (const float*)d_in[5];
    const float* b2   = (const float*)d_in[6];
    const float* W3   = (const float*)d_in[7];
    const float* b3   = (const float*)d_in[8];
    const float* ipw  = (const float*)d_in[9];
    const float* ipb  = (const float*)d_in[10];
    const float* opw  = (const float*)d_in[11];
    const float* opb  = (const float*)d_in[12];
    float* out = (float*)d_out;

    float *ph, *pa, *pb, *pqkv, *pattn, *pscores, *ppv;
    cudaGetSymbolAddress((void**)&ph, g_h);
    cudaGetSymbolAddress((void**)&pa, g_a);
    cudaGetSymbolAddress((void**)&pb, g_b);
    cudaGetSymbolAddress((void**)&pqkv, g_qkv);
    cudaGetSymbolAddress((void**)&pattn, g_attn);
    cudaGetSymbolAddress((void**)&pscores, g_scores);
    cudaGetSymbolAddress((void**)&ppv, g_pvpart);

    // --- graph preprocessing (CSR + sym norm) ---
    k_init<<<NN_ / 256, 256>>>();
    k_deg<<<EE_ / 256, 256>>>(ei, ew);
    k_dinv<<<NN_ / 256, 256>>>();
    k_scan<<<1, 1024>>>();
    k_fill<<<EE_ / 256, 256>>>(ei, ew);

    // --- layer 1: gcn ---
    tc_gemm<0, 0, 1><<<dim3(HID_ / 64, NN_ / 128, 1), 256>>>(
        x_in, 256, 0, W1, HID_, 0, nullptr, ph, HID_, 0, 0, 256, 1.0f);
    gcn_aggregate<<<NN_, HID_>>>(ph, b1, pa, HID_, 0);

    // --- mha 1 (with relu) ---
    run_mha(pa, pb, ipw, ipb, opw, opb, pqkv, pscores, pattn, ppv);

    // --- layer 2: gcn ---
    tc_gemm<0, 0, 1><<<dim3(HID_ / 64, NN_ / 128, 1), 256>>>(
        pb, HID_, 0, W2, HID_, 0, nullptr, ph, HID_, 0, 0, HID_, 1.0f);
    gcn_aggregate<<<NN_, HID_>>>(ph, b2, pa, HID_, 0);

    // --- mha 2 (with relu) ---
    run_mha(pa, pb, ipw, ipb, opw, opb, pqkv, pscores, pattn, ppv);

    // --- layer 3: gcn + sigmoid -> d_out ---
    tc_gemm<0, 0, 1><<<dim3(DOUT_ / 64, NN_ / 128, 1), 256>>>(
        pb, HID_, 0, W3, DOUT_, 0, nullptr, ph, DOUT_, 0, 0, HID_, 1.0f);
    gcn_aggregate<<<NN_, DOUT_>>>(ph, b3, out, DOUT_, 1);
}

// round 3
// speedup vs baseline: 5.1013x; 1.6984x over previous
#include <cuda_runtime.h>
#include <math.h>
#include <stdint.h>

#define NN_ 4096
#define EE_ 262144
#define HID_ 256
#define DOUT_ 128
#define HEADS_ 4
#define DH_ 64
#define L_ 4096
#define FBM_ 64
#define FBN_ 128

// ---------------- scratch (all static __device__, no allocations) ----------------
__device__ float g_deg[NN_];
__device__ float g_dinv[NN_];
__device__ int   g_cnt[NN_];
__device__ int   g_rowptr[NN_ + 1];
__device__ int   g_fill[NN_];
__device__ int   g_src[EE_];
__device__ float g_w[EE_];

__device__ float g_h[NN_ * HID_];
__device__ float g_a[NN_ * HID_];
__device__ float g_b[NN_ * HID_];
__device__ float g_qkv[NN_ * 3 * HID_];
__device__ float g_attn[NN_ * HID_];

// ---------------- preprocessing ----------------
__global__ void k_init() {
    int i = blockIdx.x * blockDim.x + threadIdx.x;
    if (i < NN_) { g_deg[i] = 1.0f; g_cnt[i] = 0; }
}

__global__ void k_deg(const int* __restrict__ ei, const float* __restrict__ ew) {
    int e = blockIdx.x * blockDim.x + threadIdx.x;
    if (e < EE_) {
        int c = ei[EE_ + e];
        atomicAdd(&g_deg[c], ew[e]);
        atomicAdd(&g_cnt[c], 1);
    }
}

__global__ void k_dinv() {
    int i = blockIdx.x * blockDim.x + threadIdx.x;
    if (i < NN_) {
        float d = g_deg[i];
        g_dinv[i] = (d > 0.f) ? rsqrtf(d) : 0.f;
    }
}

__global__ void k_scan() {
    __shared__ int partial[1024];
    int t = threadIdx.x;
    int base = t * 4;
    int c0 = g_cnt[base + 0], c1 = g_cnt[base + 1], c2 = g_cnt[base + 2], c3 = g_cnt[base + 3];
    int s = c0 + c1 + c2 + c3;
    partial[t] = s;
    __syncthreads();
    for (int off = 1; off < 1024; off <<= 1) {
        int v = 0;
        if (t >= off) v = partial[t - off];
        __syncthreads();
        partial[t] += v;
        __syncthreads();
    }
    int run = partial[t] - s;
    g_rowptr[base + 0] = run; g_fill[base + 0] = run; run += c0;
    g_rowptr[base + 1] = run; g_fill[base + 1] = run; run += c1;
    g_rowptr[base + 2] = run; g_fill[base + 2] = run; run += c2;
    g_rowptr[base + 3] = run; g_fill[base + 3] = run; run += c3;
    if (t == 1023) g_rowptr[NN_] = run;
}

__global__ void k_fill(const int* __restrict__ ei, const float* __restrict__ ew) {
    int e = blockIdx.x * blockDim.x + threadIdx.x;
    if (e < EE_) {
        int r = ei[e];
        int c = ei[EE_ + e];
        int pos = atomicAdd(&g_fill[c], 1);
        g_src[pos] = r;
        g_w[pos] = g_dinv[r] * ew[e] * g_dinv[c];
    }
}

// ---------------- tf32 helpers ----------------
__device__ __forceinline__ uint32_t f2tf(float x) {
    uint32_t u;
    asm("cvt.rna.tf32.f32 %0, %1;" : "=r"(u) : "f"(x));
    return u;
}

__device__ __forceinline__ void mma_tf32(float c[4], const uint32_t a[4], uint32_t b0, uint32_t b1) {
    asm volatile(
        "mma.sync.aligned.m16n8k8.row.col.f32.tf32.tf32.f32 "
        "{%0,%1,%2,%3}, {%4,%5,%6,%7}, {%8,%9}, {%0,%1,%2,%3};"
        : "+f"(c[0]), "+f"(c[1]), "+f"(c[2]), "+f"(c[3])
        : "r"(a[0]), "r"(a[1]), "r"(a[2]), "r"(a[3]), "r"(b0), "r"(b1));
}

// ---------------- tensor-core tf32 GEMM ----------------
// C = alpha * A @ op(B) (+bias)(+relu)
template <int TRANSB, int EPI>
__global__ void __launch_bounds__(256, 2) tc_gemm(
    const float* __restrict__ A, int lda,
    const float* __restrict__ B, int ldb,
    const float* __restrict__ bias,
    float* __restrict__ C, int ldc,
    int K, float alpha)
{
    constexpr int BM = 128, BN = 64, BK = 32, LDS_ = BK + 4;
    __shared__ uint32_t As[BM * LDS_];
    __shared__ uint32_t Bs[BN * LDS_];

    const int bm = blockIdx.y * BM;
    const int bn = blockIdx.x * BN;
    const int tid = threadIdx.x;
    const int lane = tid & 31;
    const int warp = tid >> 5;
    const int wm = (warp & 3) * 32;
    const int wn = (warp >> 2) * 32;
    const int gr = lane >> 2;
    const int gc = lane & 3;

    float acc[2][4][4];
#pragma unroll
    for (int mt = 0; mt < 2; mt++)
#pragma unroll
        for (int nt = 0; nt < 4; nt++)
#pragma unroll
            for (int q = 0; q < 4; q++) acc[mt][nt][q] = 0.f;

    for (int kt = 0; kt < K; kt += BK) {
        {
            const int m = tid >> 1;
            const int kc = (tid & 1) * 16;
            const float* p = A + (size_t)(bm + m) * lda + kt + kc;
            uint32_t* s = &As[m * LDS_ + kc];
#pragma unroll
            for (int j = 0; j < 16; j += 4) {
                float4 v = *reinterpret_cast<const float4*>(p + j);
                s[j + 0] = f2tf(v.x); s[j + 1] = f2tf(v.y);
                s[j + 2] = f2tf(v.z); s[j + 3] = f2tf(v.w);
            }
        }
        if (TRANSB) {
            const int n = tid >> 2;
            const int kc = (tid & 3) * 8;
            const float* p = B + (size_t)(bn + n) * ldb + kt + kc;
            uint32_t* s = &Bs[n * LDS_ + kc];
#pragma unroll
            for (int j = 0; j < 8; j += 4) {
                float4 v = *reinterpret_cast<const float4*>(p + j);
                s[j + 0] = f2tf(v.x); s[j + 1] = f2tf(v.y);
                s[j + 2] = f2tf(v.z); s[j + 3] = f2tf(v.w);
            }
        } else {
            const int k = tid >> 3;
            const int n0 = (tid & 7) * 8;
            const float* p = B + (size_t)(kt + k) * ldb + bn + n0;
#pragma unroll
            for (int j = 0; j < 8; j += 4) {
                float4 v = *reinterpret_cast<const float4*>(p + j);
                Bs[(n0 + j + 0) * LDS_ + k] = f2tf(v.x);
                Bs[(n0 + j + 1) * LDS_ + k] = f2tf(v.y);
                Bs[(n0 + j + 2) * LDS_ + k] = f2tf(v.z);
                Bs[(n0 + j + 3) * LDS_ + k] = f2tf(v.w);
            }
        }
        __syncthreads();

#pragma unroll
        for (int ks = 0; ks < BK; ks += 8) {
            uint32_t af[2][4];
#pragma unroll
            for (int mt = 0; mt < 2; mt++) {
                const uint32_t* a = &As[(wm + mt * 16 + gr) * LDS_ + ks + gc];
                af[mt][0] = a[0];
                af[mt][1] = a[8 * LDS_];
                af[mt][2] = a[4];
                af[mt][3] = a[8 * LDS_ + 4];
            }
#pragma unroll
            for (int nt = 0; nt < 4; nt++) {
                const uint32_t* b = &Bs[(wn + nt * 8 + gr) * LDS_ + ks + gc];
                uint32_t bf0 = b[0];
                uint32_t bf1 = b[4];
#pragma unroll
                for (int mt = 0; mt < 2; mt++)
                    mma_tf32(acc[mt][nt], af[mt], bf0, bf1);
            }
        }
        __syncthreads();
    }

#pragma unroll
    for (int mt = 0; mt < 2; mt++) {
#pragma unroll
        for (int nt = 0; nt < 4; nt++) {
            const int col = bn + wn + nt * 8 + gc * 2;
            float bx = 0.f, by = 0.f;
            if (EPI >= 1) { bx = bias[col]; by = bias[col + 1]; }
#pragma unroll
            for (int half = 0; half < 2; half++) {
                const int row = bm + wm + mt * 16 + gr + half * 8;
                float v0 = acc[mt][nt][half * 2 + 0] * alpha;
                float v1 = acc[mt][nt][half * 2 + 1] * alpha;
                if (EPI >= 1) { v0 += bx; v1 += by; }
                if (EPI == 2) { v0 = fmaxf(v0, 0.f); v1 = fmaxf(v1, 0.f); }
                *reinterpret_cast<float2*>(&C[(size_t)row * ldc + col]) = make_float2(v0, v1);
            }
        }
    }
}

// ---------------- fused flash attention (tf32 mma, online softmax) ----------------
// grid (L/FBM_, HEADS_), block 128 (4 warps x 16 query rows)
// smem: Ks[128][68] | Vs[64][132] (d-major) | Ss[64][132]
#define SM_KS 0
#define SM_VS (128 * 68)
#define SM_SS (128 * 68 + 64 * 132)
#define SM_WORDS (128 * 68 + 64 * 132 + 64 * 132)

__global__ void __launch_bounds__(128, 2) flash_attn(
    const float* __restrict__ qkv, float* __restrict__ attn)
{
    extern __shared__ uint32_t sm[];
    uint32_t* Ks = sm + SM_KS;
    uint32_t* Vs = sm + SM_VS;
    uint32_t* Ss = sm + SM_SS;

    const int h = blockIdx.y;
    const int q0 = blockIdx.x * FBM_;
    const int tid = threadIdx.x;
    const int lane = tid & 31;
    const int warp = tid >> 5;
    const int gr = lane >> 2;
    const int gc = lane & 3;
    const int wrow = warp * 16;   // warp's query-row base within tile

    // ---- Q fragments in registers, scale folded in ----
    uint32_t qf[8][4];
    {
        const float* Qb = qkv + (size_t)(q0 + wrow) * (3 * HID_) + h * DH_;
#pragma unroll
        for (int k = 0; k < 8; k++) {
            qf[k][0] = f2tf(Qb[(size_t)gr * (3 * HID_) + k * 8 + gc] * 0.125f);
            qf[k][1] = f2tf(Qb[(size_t)(gr + 8) * (3 * HID_) + k * 8 + gc] * 0.125f);
            qf[k][2] = f2tf(Qb[(size_t)gr * (3 * HID_) + k * 8 + gc + 4] * 0.125f);
            qf[k][3] = f2tf(Qb[(size_t)(gr + 8) * (3 * HID_) + k * 8 + gc + 4] * 0.125f);
        }
    }

    float o[8][4];
#pragma unroll
    for (int nt = 0; nt < 8; nt++)
#pragma unroll
        for (int q = 0; q < 4; q++) o[nt][q] = 0.f;
    float m0 = -1e30f, m1 = -1e30f, l0 = 0.f, l1 = 0.f;

    const int r8 = tid >> 4;          // 0..7
    const int c4 = (tid & 15) * 4;    // 0..60

    for (int t = 0; t < L_ / FBN_; t++) {
        // ---- stage K tile [128 x 64] and V tile transposed [64 x 128] ----
#pragma unroll
        for (int p = 0; p < 16; p++) {
            int row = p * 8 + r8;
            const float* base = qkv + (size_t)(t * FBN_ + row) * (3 * HID_) + h * DH_ + c4;
            float4 kv = *reinterpret_cast<const float4*>(base + HID_);
            uint32_t* s = &Ks[row * 68 + c4];
            s[0] = f2tf(kv.x); s[1] = f2tf(kv.y); s[2] = f2tf(kv.z); s[3] = f2tf(kv.w);
            float4 vv = *reinterpret_cast<const float4*>(base + 2 * HID_);
            Vs[(c4 + 0) * 132 + row] = f2tf(vv.x);
            Vs[(c4 + 1) * 132 + row] = f2tf(vv.y);
            Vs[(c4 + 2) * 132 + row] = f2tf(vv.z);
            Vs[(c4 + 3) * 132 + row] = f2tf(vv.w);
        }
        __syncthreads();

        // ---- S = Q @ K^T : 16 x 128 per warp ----
        float cf[16][4];
#pragma unroll
        for (int nt = 0; nt < 16; nt++) {
#pragma unroll
            for (int q = 0; q < 4; q++) cf[nt][q] = 0.f;
#pragma unroll
            for (int k = 0; k < 8; k++) {
                const uint32_t* b = &Ks[(nt * 8 + gr) * 68 + k * 8 + gc];
                mma_tf32(cf[nt], qf[k], b[0], b[4]);
            }
        }

        // ---- online softmax (rows gr and gr+8 of this warp) ----
        float vx0 = -1e30f, vx1 = -1e30f;
#pragma unroll
        for (int nt = 0; nt < 16; nt++) {
            vx0 = fmaxf(vx0, fmaxf(cf[nt][0], cf[nt][1]));
            vx1 = fmaxf(vx1, fmaxf(cf[nt][2], cf[nt][3]));
        }
        vx0 = fmaxf(vx0, __shfl_xor_sync(0xffffffffu, vx0, 1));
        vx0 = fmaxf(vx0, __shfl_xor_sync(0xffffffffu, vx0, 2));
        vx1 = fmaxf(vx1, __shfl_xor_sync(0xffffffffu, vx1, 1));
        vx1 = fmaxf(vx1, __shfl_xor_sync(0xffffffffu, vx1, 2));
        float mn0 = fmaxf(m0, vx0);
        float mn1 = fmaxf(m1, vx1);
        float corr0 = __expf(m0 - mn0);
        float corr1 = __expf(m1 - mn1);
        m0 = mn0; m1 = mn1;

        float sum0 = 0.f, sum1 = 0.f;
        uint32_t* srow0 = &Ss[(wrow + gr) * 132 + 2 * gc];
        uint32_t* srow1 = &Ss[(wrow + 8 + gr) * 132 + 2 * gc];
#pragma unroll
        for (int nt = 0; nt < 16; nt++) {
            float p00 = __expf(cf[nt][0] - m0);
            float p01 = __expf(cf[nt][1] - m0);
            float p10 = __expf(cf[nt][2] - m1);
            float p11 = __expf(cf[nt][3] - m1);
            sum0 += p00 + p01;
            sum1 += p10 + p11;
            uint2 u0 = make_uint2(f2tf(p00), f2tf(p01));
            uint2 u1 = make_uint2(f2tf(p10), f2tf(p11));
            *reinterpret_cast<uint2*>(srow0 + nt * 8) = u0;
            *reinterpret_cast<uint2*>(srow1 + nt * 8) = u1;
        }
        sum0 += __shfl_xor_sync(0xffffffffu, sum0, 1);
        sum0 += __shfl_xor_sync(0xffffffffu, sum0, 2);
        sum1 += __shfl_xor_sync(0xffffffffu, sum1, 1);
        sum1 += __shfl_xor_sync(0xffffffffu, sum1, 2);
        l0 = l0 * corr0 + sum0;
        l1 = l1 * corr1 + sum1;
#pragma unroll
        for (int nt = 0; nt < 8; nt++) {
            o[nt][0] *= corr0; o[nt][1] *= corr0;
            o[nt][2] *= corr1; o[nt][3] *= corr1;
        }
        __syncwarp();

        // ---- O += P @ V ----
#pragma unroll
        for (int kt = 0; kt < 16; kt++) {
            uint32_t af[4];
            const uint32_t* a = &Ss[(wrow + gr) * 132 + kt * 8 + gc];
            af[0] = a[0];
            af[1] = a[8 * 132];
            af[2] = a[4];
            af[3] = a[8 * 132 + 4];
#pragma unroll
            for (int nt = 0; nt < 8; nt++) {
                const uint32_t* b = &Vs[(nt * 8 + gr) * 132 + kt * 8 + gc];
                mma_tf32(o[nt], af, b[0], b[4]);
            }
        }
        __syncthreads();
    }

    // ---- epilogue: O / l -> attn ----
    float inv0 = 1.f / l0;
    float inv1 = 1.f / l1;
    float* obase = attn + (size_t)(q0 + wrow) * HID_ + h * DH_;
#pragma unroll
    for (int nt = 0; nt < 8; nt++) {
        int col = nt * 8 + 2 * gc;
        *reinterpret_cast<float2*>(obase + (size_t)gr * HID_ + col) =
            make_float2(o[nt][0] * inv0, o[nt][1] * inv0);
        *reinterpret_cast<float2*>(obase + (size_t)(gr + 8) * HID_ + col) =
            make_float2(o[nt][2] * inv1, o[nt][3] * inv1);
    }
}

// ---------------- GCN aggregation (CSR gather) ----------------
__global__ void gcn_aggregate(const float* __restrict__ h, const float* __restrict__ bias,
                              float* __restrict__ out, int dout, int act)
{
    int c = blockIdx.x;
    int f = threadIdx.x;
    float dv = g_dinv[c];
    float acc = dv * dv * h[(size_t)c * dout + f];
    int e0 = g_rowptr[c], e1 = g_rowptr[c + 1];
    for (int e = e0; e < e1; e++) {
        int s = g_src[e];
        float w = g_w[e];
        acc += w * h[(size_t)s * dout + f];
    }
    acc += bias[f];
    if (act) acc = 1.f / (1.f + __expf(-acc));
    out[(size_t)c * dout + f] = acc;
}

// ---------------- host orchestration ----------------
static void run_mha(const float* x, float* outbuf,
                    const float* ipw, const float* ipb,
                    const float* opw, const float* opb,
                    float* qkv, float* attn)
{
    // qkv = x @ in_proj_w^T + in_proj_b     [4096, 768]
    tc_gemm<1, 1><<<dim3(12, 32, 1), 256>>>(
        x, HID_, ipw, HID_, ipb, qkv, 3 * HID_, HID_, 1.0f);

    // fused attention
    flash_attn<<<dim3(L_ / FBM_, HEADS_), 128, SM_WORDS * 4>>>(qkv, attn);

    // out = relu(attn @ out_proj_w^T + out_proj_b)
    tc_gemm<1, 2><<<dim3(4, 32, 1), 256>>>(
        attn, HID_, opw, HID_, opb, outbuf, HID_, HID_, 1.0f);
}

extern "C" void kernel_launch(void* const* d_in, const int* in_sizes, int n_in,
                              void* d_out, int out_size)
{
    const float* x_in = (const float*)d_in[0];
    const int*   ei   = (const int*)d_in[1];
    const float* ew   = (const float*)d_in[2];
    const float* W1   = (const float*)d_in[3];
    const float* b1   = (const float*)d_in[4];
    const float* W2   = (const float*)d_in[5];
    const float* b2   = (const float*)d_in[6];
    const float* W3   = (const float*)d_in[7];
    const float* b3   = (const float*)d_in[8];
    const float* ipw  = (const float*)d_in[9];
    const float* ipb  = (const float*)d_in[10];
    const float* opw  = (const float*)d_in[11];
    const float* opb  = (const float*)d_in[12];
    float* out = (float*)d_out;

    float *ph, *pa, *pb, *pqkv, *pattn;
    cudaGetSymbolAddress((void**)&ph, g_h);
    cudaGetSymbolAddress((void**)&pa, g_a);
    cudaGetSymbolAddress((void**)&pb, g_b);
    cudaGetSymbolAddress((void**)&pqkv, g_qkv);
    cudaGetSymbolAddress((void**)&pattn, g_attn);

    static bool configured = false;
    if (!configured) {
        cudaFuncSetAttribute(flash_attn, cudaFuncAttributeMaxDynamicSharedMemorySize,
                             SM_WORDS * 4);
        configured = true;
    }

    // --- graph preprocessing (CSR + sym norm) ---
    k_init<<<NN_ / 256, 256>>>();
    k_deg<<<EE_ / 256, 256>>>(ei, ew);
    k_dinv<<<NN_ / 256, 256>>>();
    k_scan<<<1, 1024>>>();
    k_fill<<<EE_ / 256, 256>>>(ei, ew);

    // --- layer 1: gcn ---
    tc_gemm<0, 0><<<dim3(HID_ / 64, NN_ / 128, 1), 256>>>(
        x_in, 256, W1, HID_, nullptr, ph, HID_, 256, 1.0f);
    gcn_aggregate<<<NN_, HID_>>>(ph, b1, pa, HID_, 0);

    // --- mha 1 (with relu) ---
    run_mha(pa, pb, ipw, ipb, opw, opb, pqkv, pattn);

    // --- layer 2: gcn ---
    tc_gemm<0, 0><<<dim3(HID_ / 64, NN_ / 128, 1), 256>>>(
        pb, HID_, W2, HID_, nullptr, ph, HID_, HID_, 1.0f);
    gcn_aggregate<<<NN_, HID_>>>(ph, b2, pa, HID_, 0);

    // --- mha 2 (with relu) ---
    run_mha(pa, pb, ipw, ipb, opw, opb, pqkv, pattn);

    // --- layer 3: gcn + sigmoid -> d_out ---
    tc_gemm<0, 0><<<dim3(DOUT_ / 64, NN_ / 128, 1), 256>>>(
        pb, HID_, W3, DOUT_, nullptr, ph, DOUT_, HID_, 1.0f);
    gcn_aggregate<<<NN_, DOUT_>>>(ph, b3, out, DOUT_, 1);
}

// round 4
// speedup vs baseline: 9.9453x; 1.9496x over previous
#include <cuda_runtime.h>
#include <cuda_bf16.h>
#include <math.h>
#include <stdint.h>

#define NN_ 4096
#define EE_ 262144
#define HID_ 256
#define DOUT_ 128
#define HEADS_ 4
#define DH_ 64
#define L_ 4096
#define FBM_ 64
#define FBN_ 128
#define KST_ 36
#define VST_ 69

// ---------------- scratch (all static __device__, no allocations) ----------------
__device__ float g_deg[NN_];
__device__ float g_dinv[NN_];
__device__ int   g_cnt[NN_];
__device__ int   g_rowptr[NN_ + 1];
__device__ int   g_fill[NN_];
__device__ int   g_src[EE_];
__device__ float g_w[EE_];

__device__ float g_h[NN_ * HID_];
__device__ float g_a[NN_ * HID_];
__device__ float g_b[NN_ * HID_];
__device__ float g_attn[NN_ * HID_];
__device__ __nv_bfloat16 g_qkvb[NN_ * 3 * HID_];
__device__ float g_w1t[HID_ * 256];
__device__ float g_w2t[HID_ * HID_];
__device__ float g_w3t[DOUT_ * HID_];

// ---------------- preprocessing ----------------
__global__ void k_init() {
    int i = blockIdx.x * blockDim.x + threadIdx.x;
    if (i < NN_) { g_deg[i] = 1.0f; g_cnt[i] = 0; }
}

__global__ void k_deg(const int* __restrict__ ei, const float* __restrict__ ew) {
    int e = blockIdx.x * blockDim.x + threadIdx.x;
    if (e < EE_) {
        int c = ei[EE_ + e];
        atomicAdd(&g_deg[c], ew[e]);
        atomicAdd(&g_cnt[c], 1);
    }
}

__global__ void k_dinv() {
    int i = blockIdx.x * blockDim.x + threadIdx.x;
    if (i < NN_) {
        float d = g_deg[i];
        g_dinv[i] = (d > 0.f) ? rsqrtf(d) : 0.f;
    }
}

__global__ void k_scan() {
    __shared__ int partial[1024];
    int t = threadIdx.x;
    int base = t * 4;
    int c0 = g_cnt[base + 0], c1 = g_cnt[base + 1], c2 = g_cnt[base + 2], c3 = g_cnt[base + 3];
    int s = c0 + c1 + c2 + c3;
    partial[t] = s;
    __syncthreads();
    for (int off = 1; off < 1024; off <<= 1) {
        int v = 0;
        if (t >= off) v = partial[t - off];
        __syncthreads();
        partial[t] += v;
        __syncthreads();
    }
    int run = partial[t] - s;
    g_rowptr[base + 0] = run; g_fill[base + 0] = run; run += c0;
    g_rowptr[base + 1] = run; g_fill[base + 1] = run; run += c1;
    g_rowptr[base + 2] = run; g_fill[base + 2] = run; run += c2;
    g_rowptr[base + 3] = run; g_fill[base + 3] = run; run += c3;
    if (t == 1023) g_rowptr[NN_] = run;
}

__global__ void k_fill(const int* __restrict__ ei, const float* __restrict__ ew) {
    int e = blockIdx.x * blockDim.x + threadIdx.x;
    if (e < EE_) {
        int r = ei[e];
        int c = ei[EE_ + e];
        int pos = atomicAdd(&g_fill[c], 1);
        g_src[pos] = r;
        g_w[pos] = g_dinv[r] * ew[e] * g_dinv[c];
    }
}

// W[R][C] -> WT[C][R]
__global__ void k_transpose(const float* __restrict__ W, float* __restrict__ WT, int R, int C) {
    __shared__ float tile[32][33];
    int c0 = blockIdx.x * 32, r0 = blockIdx.y * 32;
    for (int i = threadIdx.y; i < 32; i += 8)
        tile[i][threadIdx.x] = W[(size_t)(r0 + i) * C + c0 + threadIdx.x];
    __syncthreads();
    for (int i = threadIdx.y; i < 32; i += 8)
        WT[(size_t)(c0 + i) * R + r0 + threadIdx.x] = tile[threadIdx.x][i];
}

// ---------------- bf16 helpers ----------------
__device__ __forceinline__ uint32_t packbf(float lo, float hi) {
    uint32_t u;
    asm("cvt.rn.bf16x2.f32 %0, %1, %2;" : "=r"(u) : "f"(hi), "f"(lo));
    return u;
}

__device__ __forceinline__ void mma_bf16(float c[4], const uint32_t a[4], uint32_t b0, uint32_t b1) {
    asm volatile(
        "mma.sync.aligned.m16n8k16.row.col.f32.bf16.bf16.f32 "
        "{%0,%1,%2,%3}, {%4,%5,%6,%7}, {%8,%9}, {%0,%1,%2,%3};"
        : "+f"(c[0]), "+f"(c[1]), "+f"(c[2]), "+f"(c[3])
        : "r"(a[0]), "r"(a[1]), "r"(a[2]), "r"(a[3]), "r"(b0), "r"(b1));
}

// ---------------- bf16 tensor-core GEMM:  C = A @ B^T (+bias)(+relu) ----------------
// A fp32 [M,K] row-major, B fp32 [N,K] row-major. EPI: 0 none, 1 bias, 2 bias+relu.
// OUTBF: 1 -> write bf16, 0 -> fp32.
template <int EPI, int OUTBF>
__global__ void __launch_bounds__(256) tc_gemm(
    const float* __restrict__ A, int lda,
    const float* __restrict__ B, int ldb,
    const float* __restrict__ bias,
    void* __restrict__ Cv, int ldc, int K)
{
    constexpr int BM = 128, BN = 64, BK = 32, ST = 20;  // ST in uint32 words (16 + 4 pad)
    __shared__ uint32_t As[BM * ST];
    __shared__ uint32_t Bs[BN * ST];

    const int bm = blockIdx.y * BM;
    const int bn = blockIdx.x * BN;
    const int tid = threadIdx.x;
    const int lane = tid & 31;
    const int warp = tid >> 5;
    const int wm = (warp & 3) * 32;
    const int wn = (warp >> 2) * 32;
    const int gr = lane >> 2;
    const int gc = lane & 3;

    float acc[2][4][4];
#pragma unroll
    for (int mt = 0; mt < 2; mt++)
#pragma unroll
        for (int nt = 0; nt < 4; nt++)
#pragma unroll
            for (int q = 0; q < 4; q++) acc[mt][nt][q] = 0.f;

    for (int kt = 0; kt < K; kt += BK) {
        // stage A [128 x 32] as bf16 pairs
        {
            const int m = tid >> 1;
            const int kh = (tid & 1) * 16;
            const float* p = A + (size_t)(bm + m) * lda + kt + kh;
            uint32_t* s = &As[m * ST + kh / 2];
#pragma unroll
            for (int j = 0; j < 4; j++) {
                float4 v = *reinterpret_cast<const float4*>(p + j * 4);
                s[j * 2 + 0] = packbf(v.x, v.y);
                s[j * 2 + 1] = packbf(v.z, v.w);
            }
        }
        // stage B [64 x 32] as bf16 pairs
        {
            const int n = tid >> 2;
            const int kh = (tid & 3) * 8;
            const float* p = B + (size_t)(bn + n) * ldb + kt + kh;
            uint32_t* s = &Bs[n * ST + kh / 2];
            float4 v0 = *reinterpret_cast<const float4*>(p);
            float4 v1 = *reinterpret_cast<const float4*>(p + 4);
            s[0] = packbf(v0.x, v0.y);
            s[1] = packbf(v0.z, v0.w);
            s[2] = packbf(v1.x, v1.y);
            s[3] = packbf(v1.z, v1.w);
        }
        __syncthreads();

#pragma unroll
        for (int kc = 0; kc < 2; kc++) {
            uint32_t af[2][4];
#pragma unroll
            for (int mt = 0; mt < 2; mt++) {
                const uint32_t* a = &As[(wm + mt * 16 + gr) * ST + kc * 8 + gc];
                af[mt][0] = a[0];
                af[mt][1] = a[8 * ST];
                af[mt][2] = a[4];
                af[mt][3] = a[8 * ST + 4];
            }
#pragma unroll
            for (int nt = 0; nt < 4; nt++) {
                const uint32_t* b = &Bs[(wn + nt * 8 + gr) * ST + kc * 8 + gc];
                uint32_t b0 = b[0], b1 = b[4];
#pragma unroll
                for (int mt = 0; mt < 2; mt++)
                    mma_bf16(acc[mt][nt], af[mt], b0, b1);
            }
        }
        __syncthreads();
    }

#pragma unroll
    for (int mt = 0; mt < 2; mt++) {
#pragma unroll
        for (int nt = 0; nt < 4; nt++) {
            const int col = bn + wn + nt * 8 + gc * 2;
            float bx = 0.f, by = 0.f;
            if (EPI >= 1) { bx = bias[col]; by = bias[col + 1]; }
#pragma unroll
            for (int half = 0; half < 2; half++) {
                const int row = bm + wm + mt * 16 + gr + half * 8;
                float v0 = acc[mt][nt][half * 2 + 0];
                float v1 = acc[mt][nt][half * 2 + 1];
                if (EPI >= 1) { v0 += bx; v1 += by; }
                if (EPI == 2) { v0 = fmaxf(v0, 0.f); v1 = fmaxf(v1, 0.f); }
                if (OUTBF) {
                    __nv_bfloat16* C = (__nv_bfloat16*)Cv;
                    *reinterpret_cast<uint32_t*>(&C[(size_t)row * ldc + col]) = packbf(v0, v1);
                } else {
                    float* C = (float*)Cv;
                    *reinterpret_cast<float2*>(&C[(size_t)row * ldc + col]) = make_float2(v0, v1);
                }
            }
        }
    }
}

// ---------------- fused flash attention (bf16 mma, online softmax, P in registers) ----------------
// grid (L/FBM_, HEADS_), block 128 (4 warps x 16 query rows)
__global__ void __launch_bounds__(128) flash_attn(
    const __nv_bfloat16* __restrict__ qkvb, float* __restrict__ attn)
{
    __shared__ uint32_t Ks[128 * KST_];   // [key][dh-pair], pairs along dh
    __shared__ uint32_t Vs[64 * VST_];    // [dh][key-pair], pairs along key

    const int h = blockIdx.y;
    const int q0 = blockIdx.x * FBM_;
    const int tid = threadIdx.x;
    const int lane = tid & 31;
    const int warp = tid >> 5;
    const int gr = lane >> 2;
    const int gc = lane & 3;
    const int wrow = warp * 16;

    // ---- Q fragments (raw bf16, scale folded into softmax) ----
    uint32_t qf[4][4];
    {
        const uint32_t* q0p = reinterpret_cast<const uint32_t*>(
            qkvb + (size_t)(q0 + wrow + gr) * (3 * HID_) + h * DH_);
        const uint32_t* q1p = reinterpret_cast<const uint32_t*>(
            qkvb + (size_t)(q0 + wrow + gr + 8) * (3 * HID_) + h * DH_);
#pragma unroll
        for (int kc = 0; kc < 4; kc++) {
            qf[kc][0] = q0p[kc * 8 + gc];
            qf[kc][1] = q1p[kc * 8 + gc];
            qf[kc][2] = q0p[kc * 8 + gc + 4];
            qf[kc][3] = q1p[kc * 8 + gc + 4];
        }
    }

    float o[8][4];
#pragma unroll
    for (int nt = 0; nt < 8; nt++)
#pragma unroll
        for (int q = 0; q < 4; q++) o[nt][q] = 0.f;
    float m0 = -1e30f, m1 = -1e30f, l0 = 0.f, l1 = 0.f;

    const int r8 = tid >> 3;   // 0..15
    const int c8 = tid & 7;    // 0..7

    for (int t = 0; t < L_ / FBN_; t++) {
        // ---- stage K [128 x 64] bf16 ----
#pragma unroll
        for (int p = 0; p < 8; p++) {
            int row = p * 16 + r8;
            const uint4 kv = *reinterpret_cast<const uint4*>(
                qkvb + (size_t)(t * FBN_ + row) * (3 * HID_) + HID_ + h * DH_ + c8 * 8);
            *reinterpret_cast<uint4*>(&Ks[row * KST_ + c8 * 4]) = kv;
        }
        // ---- stage V transposed: Vs[dh][key-pair] ----
#pragma unroll
        for (int p = 0; p < 4; p++) {
            int j = p * 16 + r8;       // key pair index
            const __nv_bfloat16* base =
                qkvb + (size_t)(t * FBN_ + 2 * j) * (3 * HID_) + 2 * HID_ + h * DH_ + c8 * 8;
            uint4 r0 = *reinterpret_cast<const uint4*>(base);
            uint4 r1 = *reinterpret_cast<const uint4*>(base + 3 * HID_);
            uint32_t* vb = &Vs[(c8 * 8) * VST_ + j];
            vb[0 * VST_] = __byte_perm(r0.x, r1.x, 0x5410);
            vb[1 * VST_] = __byte_perm(r0.x, r1.x, 0x7632);
            vb[2 * VST_] = __byte_perm(r0.y, r1.y, 0x5410);
            vb[3 * VST_] = __byte_perm(r0.y, r1.y, 0x7632);
            vb[4 * VST_] = __byte_perm(r0.z, r1.z, 0x5410);
            vb[5 * VST_] = __byte_perm(r0.z, r1.z, 0x7632);
            vb[6 * VST_] = __byte_perm(r0.w, r1.w, 0x5410);
            vb[7 * VST_] = __byte_perm(r0.w, r1.w, 0x7632);
        }
        __syncthreads();

        // ---- S = Q @ K^T (raw scores, fp32 accum) ----
        float cf[16][4];
#pragma unroll
        for (int nt = 0; nt < 16; nt++) {
#pragma unroll
            for (int q = 0; q < 4; q++) cf[nt][q] = 0.f;
#pragma unroll
            for (int kc = 0; kc < 4; kc++) {
                const uint32_t* b = &Ks[(nt * 8 + gr) * KST_ + kc * 8 + gc];
                mma_bf16(cf[nt], qf[kc], b[0], b[4]);
            }
        }

        // ---- online softmax (scale 0.125 applied here) ----
        float vx0 = -1e30f, vx1 = -1e30f;
#pragma unroll
        for (int nt = 0; nt < 16; nt++) {
            vx0 = fmaxf(vx0, fmaxf(cf[nt][0], cf[nt][1]));
            vx1 = fmaxf(vx1, fmaxf(cf[nt][2], cf[nt][3]));
        }
        vx0 = fmaxf(vx0, __shfl_xor_sync(0xffffffffu, vx0, 1));
        vx0 = fmaxf(vx0, __shfl_xor_sync(0xffffffffu, vx0, 2));
        vx1 = fmaxf(vx1, __shfl_xor_sync(0xffffffffu, vx1, 1));
        vx1 = fmaxf(vx1, __shfl_xor_sync(0xffffffffu, vx1, 2));
        float mn0 = fmaxf(m0, 0.125f * vx0);
        float mn1 = fmaxf(m1, 0.125f * vx1);
        float corr0 = __expf(m0 - mn0);
        float corr1 = __expf(m1 - mn1);
        m0 = mn0; m1 = mn1;

        uint32_t pf[8][4];
        float sum0 = 0.f, sum1 = 0.f;
#pragma unroll
        for (int nt = 0; nt < 16; nt++) {
            float p00 = __expf(fmaf(0.125f, cf[nt][0], -m0));
            float p01 = __expf(fmaf(0.125f, cf[nt][1], -m0));
            float p10 = __expf(fmaf(0.125f, cf[nt][2], -m1));
            float p11 = __expf(fmaf(0.125f, cf[nt][3], -m1));
            sum0 += p00 + p01;
            sum1 += p10 + p11;
            if ((nt & 1) == 0) {
                pf[nt >> 1][0] = packbf(p00, p01);
                pf[nt >> 1][1] = packbf(p10, p11);
            } else {
                pf[nt >> 1][2] = packbf(p00, p01);
                pf[nt >> 1][3] = packbf(p10, p11);
            }
        }
        sum0 += __shfl_xor_sync(0xffffffffu, sum0, 1);
        sum0 += __shfl_xor_sync(0xffffffffu, sum0, 2);
        sum1 += __shfl_xor_sync(0xffffffffu, sum1, 1);
        sum1 += __shfl_xor_sync(0xffffffffu, sum1, 2);
        l0 = l0 * corr0 + sum0;
        l1 = l1 * corr1 + sum1;
#pragma unroll
        for (int nt = 0; nt < 8; nt++) {
            o[nt][0] *= corr0; o[nt][1] *= corr0;
            o[nt][2] *= corr1; o[nt][3] *= corr1;
        }

        // ---- O += P @ V  (P straight from registers) ----
#pragma unroll
        for (int kc = 0; kc < 8; kc++) {
#pragma unroll
            for (int nt = 0; nt < 8; nt++) {
                const uint32_t* b = &Vs[(nt * 8 + gr) * VST_ + kc * 8 + gc];
                mma_bf16(o[nt], pf[kc], b[0], b[4]);
            }
        }
        __syncthreads();
    }

    // ---- epilogue: O / l -> attn (fp32) ----
    float inv0 = 1.f / l0;
    float inv1 = 1.f / l1;
    float* obase = attn + (size_t)(q0 + wrow) * HID_ + h * DH_;
#pragma unroll
    for (int nt = 0; nt < 8; nt++) {
        int col = nt * 8 + 2 * gc;
        *reinterpret_cast<float2*>(obase + (size_t)gr * HID_ + col) =
            make_float2(o[nt][0] * inv0, o[nt][1] * inv0);
        *reinterpret_cast<float2*>(obase + (size_t)(gr + 8) * HID_ + col) =
            make_float2(o[nt][2] * inv1, o[nt][3] * inv1);
    }
}

// ---------------- GCN aggregation (CSR gather, float4) ----------------
__global__ void gcn_aggregate4(const float4* __restrict__ h4, const float* __restrict__ bias,
                               float4* __restrict__ out4, int dout4, int act)
{
    int c = blockIdx.x;
    int f = threadIdx.x;
    float dv = g_dinv[c];
    float s = dv * dv;
    float4 acc = h4[(size_t)c * dout4 + f];
    acc.x *= s; acc.y *= s; acc.z *= s; acc.w *= s;
    int e0 = g_rowptr[c], e1 = g_rowptr[c + 1];
    int e = e0;
    for (; e + 2 <= e1; e += 2) {
        int s0 = g_src[e], s1 = g_src[e + 1];
        float w0 = g_w[e], w1 = g_w[e + 1];
        float4 v0 = h4[(size_t)s0 * dout4 + f];
        float4 v1 = h4[(size_t)s1 * dout4 + f];
        acc.x += w0 * v0.x + w1 * v1.x;
        acc.y += w0 * v0.y + w1 * v1.y;
        acc.z += w0 * v0.z + w1 * v1.z;
        acc.w += w0 * v0.w + w1 * v1.w;
    }
    if (e < e1) {
        int s0 = g_src[e];
        float w0 = g_w[e];
        float4 v0 = h4[(size_t)s0 * dout4 + f];
        acc.x += w0 * v0.x; acc.y += w0 * v0.y;
        acc.z += w0 * v0.z; acc.w += w0 * v0.w;
    }
    const float4 b4 = *reinterpret_cast<const float4*>(bias + f * 4);
    acc.x += b4.x; acc.y += b4.y; acc.z += b4.z; acc.w += b4.w;
    if (act) {
        acc.x = 1.f / (1.f + __expf(-acc.x));
        acc.y = 1.f / (1.f + __expf(-acc.y));
        acc.z = 1.f / (1.f + __expf(-acc.z));
        acc.w = 1.f / (1.f + __expf(-acc.w));
    }
    out4[(size_t)c * dout4 + f] = acc;
}

// ---------------- host orchestration ----------------
static void run_mha(const float* x, float* outbuf,
                    const float* ipw, const float* ipb,
                    const float* opw, const float* opb,
                    __nv_bfloat16* qkvb, float* attn)
{
    // qkvb = bf16(x @ in_proj_w^T + in_proj_b)   [4096, 768]
    tc_gemm<1, 1><<<dim3(12, 32), 256>>>(
        x, HID_, ipw, HID_, ipb, qkvb, 3 * HID_, HID_);

    flash_attn<<<dim3(L_ / FBM_, HEADS_), 128>>>(qkvb, attn);

    // out = relu(attn @ out_proj_w^T + out_proj_b)
    tc_gemm<2, 0><<<dim3(4, 32), 256>>>(
        attn, HID_, opw, HID_, opb, outbuf, HID_, HID_);
}

extern "C" void kernel_launch(void* const* d_in, const int* in_sizes, int n_in,
                              void* d_out, int out_size)
{
    const float* x_in = (const float*)d_in[0];
    const int*   ei   = (const int*)d_in[1];
    const float* ew   = (const float*)d_in[2];
    const float* W1   = (const float*)d_in[3];
    const float* b1   = (const float*)d_in[4];
    const float* W2   = (const float*)d_in[5];
    const float* b2   = (const float*)d_in[6];
    const float* W3   = (const float*)d_in[7];
    const float* b3   = (const float*)d_in[8];
    const float* ipw  = (const float*)d_in[9];
    const float* ipb  = (const float*)d_in[10];
    const float* opw  = (const float*)d_in[11];
    const float* opb  = (const float*)d_in[12];
    float* out = (float*)d_out;

    float *ph, *pa, *pb, *pattn, *pw1t, *pw2t, *pw3t;
    __nv_bfloat16* pqkvb;
    cudaGetSymbolAddress((void**)&ph, g_h);
    cudaGetSymbolAddress((void**)&pa, g_a);
    cudaGetSymbolAddress((void**)&pb, g_b);
    cudaGetSymbolAddress((void**)&pattn, g_attn);
    cudaGetSymbolAddress((void**)&pqkvb, g_qkvb);
    cudaGetSymbolAddress((void**)&pw1t, g_w1t);
    cudaGetSymbolAddress((void**)&pw2t, g_w2t);
    cudaGetSymbolAddress((void**)&pw3t, g_w3t);

    // --- weight transposes (W [K,N] -> WT [N,K]) ---
    k_transpose<<<dim3(HID_ / 32, 256 / 32), dim3(32, 8)>>>(W1, pw1t, 256, HID_);
    k_transpose<<<dim3(HID_ / 32, HID_ / 32), dim3(32, 8)>>>(W2, pw2t, HID_, HID_);
    k_transpose<<<dim3(DOUT_ / 32, HID_ / 32), dim3(32, 8)>>>(W3, pw3t, HID_, DOUT_);

    // --- graph preprocessing (CSR + sym norm) ---
    k_init<<<NN_ / 256, 256>>>();
    k_deg<<<EE_ / 256, 256>>>(ei, ew);
    k_dinv<<<NN_ / 256, 256>>>();
    k_scan<<<1, 1024>>>();
    k_fill<<<EE_ / 256, 256>>>(ei, ew);

    // --- layer 1: gcn ---
    tc_gemm<0, 0><<<dim3(HID_ / 64, NN_ / 128), 256>>>(
        x_in, 256, pw1t, 256, nullptr, ph, HID_, 256);
    gcn_aggregate4<<<NN_, HID_ / 4>>>((const float4*)ph, b1, (float4*)pa, HID_ / 4, 0);

    // --- mha 1 (with relu) ---
    run_mha(pa, pb, ipw, ipb, opw, opb, pqkvb, pattn);

    // --- layer 2: gcn ---
    tc_gemm<0, 0><<<dim3(HID_ / 64, NN_ / 128), 256>>>(
        pb, HID_, pw2t, HID_, nullptr, ph, HID_, HID_);
    gcn_aggregate4<<<NN_, HID_ / 4>>>((const float4*)ph, b2, (float4*)pa, HID_ / 4, 0);

    // --- mha 2 (with relu) ---
    run_mha(pa, pb, ipw, ipb, opw, opb, pqkvb, pattn);

    // --- layer 3: gcn + sigmoid -> d_out ---
    tc_gemm<0, 0><<<dim3(DOUT_ / 64, NN_ / 128), 256>>>(
        pb, HID_, pw3t, HID_, nullptr, ph, DOUT_, HID_);
    gcn_aggregate4<<<NN_, DOUT_ / 4>>>((const float4*)ph, b3, (float4*)out, DOUT_ / 4, 1);
}